// round 13
// baseline (speedup 1.0000x reference)
#include <cuda_runtime.h>
#include <cuda_bf16.h>
#include <math.h>

#define BB 4096
#define LL 200
#define FF 8
#define DD 64
#define KK 15

__device__ unsigned g_simEnc[BB * LL];   // 3.28 MB scratch: encoded sims

__device__ __forceinline__ unsigned enc_f(float f) {
    unsigned u = __float_as_uint(f);
    return (u >> 31) ? ~u : (u ^ 0x80000000u);
}
__device__ __forceinline__ float dec_f(unsigned u) {
    unsigned bits = (u & 0x80000000u) ? (u ^ 0x80000000u) : ~u;
    return __uint_as_float(bits);
}

// ---------------- Kernel 1: cosine sims, no smem, no barriers ----------------
__global__ void __launch_bounds__(256) sim_kernel(
    const int* __restrict__ x,
    const int* __restrict__ self_loc,
    const float* __restrict__ E)
{
    const int b  = blockIdx.y;
    const int sl = __ldg(self_loc + b);
    const int l0 = blockIdx.x << 5;          // 32 rows per block
    if (l0 >= sl) return;                    // uniform exit: nothing to compute

    const int tid  = threadIdx.x;
    const int warp = tid >> 5;
    const int lane = tid & 31;
    const int grp  = lane >> 3;              // 4 rows per warp
    const int gl   = lane & 7;               // 32B slice pair within row

    const int* xb = x + (size_t)b * (LL * FF);

    // self row slices in registers (broadcast loads across groups)
    const int cs = __ldg(xb + sl * FF + 5);
    const float4* sp = reinterpret_cast<const float4*>(E + (size_t)cs * DD);
    const float4 sa = __ldg(sp + gl);
    const float4 sb = __ldg(sp + gl + 8);
    float q = sa.x*sa.x + sa.y*sa.y + sa.z*sa.z + sa.w*sa.w
            + sb.x*sb.x + sb.y*sb.y + sb.z*sb.z + sb.w*sb.w;
    q += __shfl_xor_sync(0xffffffffu, q, 4);
    q += __shfl_xor_sync(0xffffffffu, q, 2);
    q += __shfl_xor_sync(0xffffffffu, q, 1);
    const float inv_nself = rsqrtf(q + 1e-8f);

    // this thread's row (branch-free compute; guarded write only)
    const int l  = l0 + (warp << 2) + grp;
    const int lc = (l < sl) ? l : 0;         // clamp for safe loads
    const int c = __ldg(xb + lc * FF + 5);
    const float4* rp = reinterpret_cast<const float4*>(E + (size_t)c * DD);
    const float4 va = __ldg(rp + gl);
    const float4 vb = __ldg(rp + gl + 8);
    float dot = va.x*sa.x + va.y*sa.y + va.z*sa.z + va.w*sa.w
              + vb.x*sb.x + vb.y*sb.y + vb.z*sb.z + vb.w*sb.w;
    float ssq = va.x*va.x + va.y*va.y + va.z*va.z + va.w*va.w
              + vb.x*vb.x + vb.y*vb.y + vb.z*vb.z + vb.w*vb.w;
    dot += __shfl_xor_sync(0xffffffffu, dot, 4);
    ssq += __shfl_xor_sync(0xffffffffu, ssq, 4);
    dot += __shfl_xor_sync(0xffffffffu, dot, 2);
    ssq += __shfl_xor_sync(0xffffffffu, ssq, 2);
    dot += __shfl_xor_sync(0xffffffffu, dot, 1);
    ssq += __shfl_xor_sync(0xffffffffu, ssq, 1);
    const float sim = dot * rsqrtf(ssq + 1e-8f) * inv_nself;

    if (l < sl && gl == 0)
        g_simEnc[b * LL + l] = enc_f(sim);
}

// ---------------- Kernel 2: top-k select + outputs (round-12 back half) -------
__global__ void __launch_bounds__(256) topk_kernel(
    const int* __restrict__ x,
    const int* __restrict__ self_loc,
    float* __restrict__ out)
{
    __shared__ __align__(16) unsigned simk[224];
    __shared__ unsigned long long selKey[KK];
    __shared__ int sortedL[KK + 1];

    const int b   = blockIdx.x;
    const int tid = threadIdx.x;

    const int* xb = x + (size_t)b * (LL * FF);
    const int sl = __ldg(self_loc + b);

    const unsigned e = (tid < sl) ? __ldg(&g_simEnc[b * LL + tid]) : 0u;
    const unsigned long long myKey =
        ((unsigned long long)e << 32) | (unsigned)(LL - 1 - tid);
    if (tid < 224) simk[tid] = e;            // pads = 0, can never out-rank
    __syncthreads();

    // rank-select among first sl keys (32-bit fast path)
    int rank = LL;
    if (tid < sl) {
        int r = 0;
        const uint4* p = reinterpret_cast<const uint4*>(simk);
        const int nj = (sl + 3) >> 2;
        for (int j = 0; j < nj; ++j) {        // broadcast LDS.128
            const uint4 k = p[j];
            r += (k.x > e);
            r += (k.y > e);
            r += (k.z > e);
            r += (k.w > e);
        }
        rank = r;
        if (r < KK) selKey[r] = myKey;
    }
    __syncthreads();

    // tie inside top-K -> shared slot -> loser detects; rare exact recount
    const int pred = (rank < KK) && (selKey[rank] != myKey);
    if (__syncthreads_or(pred)) {
        if (tid < sl) {
            int r2 = 0;
            for (int j = 0; j < sl; ++j) {
                const unsigned ej = simk[j];
                r2 += (ej > e) || (ej == e && j < tid);
            }
            if (r2 < KK) selKey[r2] = myKey;
        }
        __syncthreads();
    }

    // sort the 15 selected by ascending index; emit sim_topk
    if (tid < KK) {
        const unsigned long long mk = selKey[tid];
        const unsigned myLow = (unsigned)mk;   // 199 - l (larger = smaller l)
        int pos = 0;
        #pragma unroll
        for (int j = 0; j < KK; ++j) pos += ((unsigned)selKey[j] > myLow);
        const int l = LL - 1 - (int)myLow;
        sortedL[pos] = l;
        out[(size_t)BB * ((KK + 1) * FF) + (size_t)b * KK + pos] = dec_f((unsigned)(mk >> 32));
    }
    if (tid == KK) sortedL[KK] = sl;
    __syncthreads();

    // x_out: [16 rows x 8 feats] as float
    if (tid < (KK + 1) * FF) {
        const int r = tid >> 3;
        const int f = tid & 7;
        const int l = sortedL[r];
        out[(size_t)b * ((KK + 1) * FF) + tid] = (float)__ldg(xb + l * FF + f);
    }
}

extern "C" void kernel_launch(void* const* d_in, const int* in_sizes, int n_in,
                              void* d_out, int out_size) {
    const int*   x  = (const int*)d_in[0];   // x: [4096, 200, 8] int32
    const int*   sl = (const int*)d_in[1];   // self_loc: [4096] int32
    const float* E  = (const float*)d_in[2]; // E: [100001, 64] float32
    float* out = (float*)d_out;

    sim_kernel<<<dim3(7, BB), 256>>>(x, sl, E);
    topk_kernel<<<BB, 256>>>(x, sl, out);
}

// round 14
// speedup vs baseline: 1.5997x; 1.5997x over previous
#include <cuda_runtime.h>
#include <cuda_bf16.h>
#include <math.h>

#define BB 4096
#define LL 200
#define FF 8
#define DD 64
#define KK 15
// dynamic smem: per-row partials [200][8] float2 (each = dot/ssq over 8 floats)
#define SMEM_BYTES (LL * 8 * 8)   // 12800 B

typedef unsigned long long u64;

#define MUL2(d, a, b)    asm("mul.rn.f32x2 %0, %1, %2;"     : "=l"(d) : "l"(a), "l"(b))
#define FMA2(d, a, b, c) asm("fma.rn.f32x2 %0, %1, %2, %3;" : "=l"(d) : "l"(a), "l"(b), "l"(c))

union F4U2 { float4 f4; u64 u2[2]; };

__device__ __forceinline__ float2 unpack2(u64 v) {
    float2 r;
    asm("mov.b64 {%0, %1}, %2;" : "=f"(r.x), "=f"(r.y) : "l"(v));
    return r;
}

__device__ __forceinline__ unsigned enc_f(float f) {
    unsigned u = __float_as_uint(f);
    return (u >> 31) ? ~u : (u ^ 0x80000000u);
}
__device__ __forceinline__ float dec_f(unsigned u) {
    unsigned bits = (u & 0x80000000u) ? (u ^ 0x80000000u) : ~u;
    return __uint_as_float(bits);
}

__global__ void __launch_bounds__(256, 8) search_predict_kernel(
    const int* __restrict__ x,        // [B, L, F] int32
    const int* __restrict__ self_loc, // [B] int32
    const float* __restrict__ E,      // [NFEAT+1, D] float32
    float* __restrict__ out)          // [B*16*8] x_out-as-float, then [B*15] sim_topk
{
    extern __shared__ __align__(16) float partials[];   // [200][8] float2, rot-swizzled

    __shared__ __align__(16) float4 selfv[16];          // self embedding row
    __shared__ int catS[LL];
    __shared__ __align__(16) unsigned simk[224];        // 32-bit encoded sims
    __shared__ unsigned long long selKey[KK];
    __shared__ int sortedL[KK + 1];
    __shared__ float invns;

    const int b    = blockIdx.x;
    const int tid  = threadIdx.x;
    const int warp = tid >> 5;

    const int* xb = x + (size_t)b * (LL * FF);
    const int sl = __ldg(self_loc + b);

    // catS for rows <= sl only; warp 7 loads self row + precomputes inv-norm
    if (tid <= sl) catS[tid] = __ldg(xb + tid * FF + 5);
    if (warp == 7) {
        const int hl = tid & 15;
        if ((tid & 31) < 16) {
            const int cs = __ldg(xb + sl * FF + 5);
            selfv[hl] = __ldg(reinterpret_cast<const float4*>(E + (size_t)cs * DD) + hl);
        }
        __syncwarp();
        const float4 s = selfv[hl];                       // lanes 16-31 mirror 0-15
        float q = s.x * s.x + s.y * s.y + s.z * s.z + s.w * s.w;
        q += __shfl_xor_sync(0xffffffffu, q, 8);
        q += __shfl_xor_sync(0xffffffffu, q, 4);
        q += __shfl_xor_sync(0xffffffffu, q, 2);
        q += __shfl_xor_sync(0xffffffffu, q, 1);
        if (tid == 224) invns = rsqrtf(q + 1e-8f);
    }
    __syncthreads();

    // ---- Phase A: fused gather + partials (packed f32x2 math), rows l <= sl ----
    {
        const int rg = tid >> 3;          // row within 32-row tile
        const int j8 = tid & 7;           // owns float4 slices j8 and j8+8
        F4U2 sa, sb;
        sa.f4 = selfv[j8];
        sb.f4 = selfv[j8 + 8];
        const u64 sa0 = sa.u2[0], sa1 = sa.u2[1];
        const u64 sb0 = sb.u2[0], sb1 = sb.u2[1];
        #pragma unroll
        for (int it = 0; it < 7; ++it) {
            const int l = it * 32 + rg;
            if (l <= sl) {                // warp-uniform except one boundary warp
                const int c = catS[l];
                const float4* rp = reinterpret_cast<const float4*>(E + (size_t)c * DD);
                F4U2 va, vb;
                va.f4 = __ldg(rp + j8);
                vb.f4 = __ldg(rp + j8 + 8);
                u64 d2, q2;
                MUL2(d2, va.u2[0], sa0);
                FMA2(d2, va.u2[1], sa1, d2);
                FMA2(d2, vb.u2[0], sb0, d2);
                FMA2(d2, vb.u2[1], sb1, d2);
                MUL2(q2, va.u2[0], va.u2[0]);
                FMA2(q2, va.u2[1], va.u2[1], q2);
                FMA2(q2, vb.u2[0], vb.u2[0], q2);
                FMA2(q2, vb.u2[1], vb.u2[1], q2);
                const float2 dd = unpack2(d2);
                const float2 qq = unpack2(q2);
                // rotation swizzle: partial j8 of row l -> 16B chunk ((j8>>1)+(l>>1))&3
                const int byteoff = l * 64 + ((((j8 >> 1) + (l >> 1)) & 3) << 4)
                                  + ((j8 & 1) << 3);
                *reinterpret_cast<float2*>(reinterpret_cast<char*>(partials) + byteoff)
                    = make_float2(dd.x + dd.y, qq.x + qq.y);
            }
        }
    }
    __syncthreads();

    // ---- Phase B: thread-per-row reduction, only rows <= sl ----
    float dot = 0.f, ssq = 0.f;
    if (tid <= sl) {
        const char* base = reinterpret_cast<const char*>(partials) + tid * 64;
        const int rot = (tid >> 1) & 3;
        #pragma unroll
        for (int k = 0; k < 4; ++k) {     // logical chunk order fixed (bit-exact dups)
            const float4 c = *reinterpret_cast<const float4*>(base + (((k + rot) & 3) << 4));
            dot += c.x + c.z;
            ssq += c.y + c.w;
        }
    }
    const float sim = (tid < sl) ? dot * rsqrtf(ssq + 1e-8f) * invns : -2.0f;
    const unsigned e = enc_f(sim);
    const unsigned long long myKey =
        ((unsigned long long)e << 32) | (unsigned)(LL - 1 - tid);
    if (tid < 224) simk[tid] = e;          // 200..223 pad = enc(-2), inert
    __syncthreads();

    // ---- rank-select among the first sl keys only (32-bit fast path) ----
    int rank = LL;
    if (tid < sl) {
        int r = 0;
        const uint4* p = reinterpret_cast<const uint4*>(simk);
        const int nj = (sl + 3) >> 2;
        for (int j = 0; j < nj; ++j) {            // broadcast LDS.128
            const uint4 k = p[j];
            r += (k.x > e);
            r += (k.y > e);
            r += (k.z > e);
            r += (k.w > e);
        }
        rank = r;
        if (r < KK) selKey[r] = myKey;
    }
    __syncthreads();                               // publish selKey

    // tie inside top-K -> two threads shared a slot -> loser detects; rare
    const int pred = (rank < KK) && (selKey[rank] != myKey);
    if (__syncthreads_or(pred)) {
        // exact tie-aware recount; key_j > myKey  <=>  ej > e || (ej == e && j < tid)
        if (tid < sl) {
            int r2 = 0;
            for (int j = 0; j < sl; ++j) {
                const unsigned ej = simk[j];
                r2 += (ej > e) || (ej == e && j < tid);
            }
            if (r2 < KK) selKey[r2] = myKey;
        }
        __syncthreads();
    }

    // ---- sort the 15 selected by ascending index; emit sim_topk ----
    if (tid < KK) {
        const unsigned long long mk = selKey[tid];
        const unsigned myLow = (unsigned)mk;        // 199 - l (larger = smaller l)
        int pos = 0;
        #pragma unroll
        for (int j = 0; j < KK; ++j) pos += ((unsigned)selKey[j] > myLow);
        const int l = LL - 1 - (int)myLow;
        sortedL[pos] = l;
        out[(size_t)BB * ((KK + 1) * FF) + (size_t)b * KK + pos] = dec_f((unsigned)(mk >> 32));
    }
    if (tid == KK) sortedL[KK] = sl;
    __syncthreads();

    // ---- x_out: [16 rows x 8 feats] as float, vectorized (one warp) ----
    if (tid < 32) {
        const int r    = tid >> 1;                 // output row 0..15
        const int half = tid & 1;                  // 4-int half of the row
        const int l = sortedL[r];
        const int4 v = __ldg(reinterpret_cast<const int4*>(xb + l * FF) + half);
        const float4 f = make_float4((float)v.x, (float)v.y, (float)v.z, (float)v.w);
        reinterpret_cast<float4*>(out + (size_t)b * ((KK + 1) * FF))[tid] = f;
    }
}

extern "C" void kernel_launch(void* const* d_in, const int* in_sizes, int n_in,
                              void* d_out, int out_size) {
    const int*   x  = (const int*)d_in[0];   // x: [4096, 200, 8] int32
    const int*   sl = (const int*)d_in[1];   // self_loc: [4096] int32
    const float* E  = (const float*)d_in[2]; // E: [100001, 64] float32
    float* out = (float*)d_out;

    search_predict_kernel<<<BB, 256, SMEM_BYTES>>>(x, sl, E, out);
}

// round 15
// speedup vs baseline: 1.6039x; 1.0026x over previous
#include <cuda_runtime.h>
#include <cuda_bf16.h>
#include <math.h>

#define BB 4096
#define LL 200
#define FF 8
#define DD 64
#define KK 15
// dynamic smem: per-row partials [200][8] float2 (each = dot/ssq over 8 floats)
#define SMEM_BYTES (LL * 8 * 8)   // 12800 B

typedef unsigned long long u64;

#define MUL2(d, a, b)    asm("mul.rn.f32x2 %0, %1, %2;"     : "=l"(d) : "l"(a), "l"(b))
#define FMA2(d, a, b, c) asm("fma.rn.f32x2 %0, %1, %2, %3;" : "=l"(d) : "l"(a), "l"(b), "l"(c))

union F4U2 { float4 f4; u64 u2[2]; };

__device__ __forceinline__ float2 unpack2(u64 v) {
    float2 r;
    asm("mov.b64 {%0, %1}, %2;" : "=f"(r.x), "=f"(r.y) : "l"(v));
    return r;
}

__global__ void __launch_bounds__(256, 8) search_predict_kernel(
    const int* __restrict__ x,        // [B, L, F] int32
    const int* __restrict__ self_loc, // [B] int32
    const float* __restrict__ E,      // [NFEAT+1, D] float32
    float* __restrict__ out)          // [B*16*8] x_out-as-float, then [B*15] sim_topk
{
    extern __shared__ __align__(16) float partials[];   // [200][8] float2, rot-swizzled

    __shared__ __align__(16) float4 selfv[16];          // self embedding row
    __shared__ int catS[LL];
    __shared__ __align__(16) float simF[224];           // raw float sims (no NaNs)
    __shared__ unsigned long long selKey[KK];           // {float bits, 199 - l}
    __shared__ int sortedL[KK + 1];
    __shared__ float invns;

    const int b    = blockIdx.x;
    const int tid  = threadIdx.x;
    const int warp = tid >> 5;

    const int* xb = x + (size_t)b * (LL * FF);
    const int sl = __ldg(self_loc + b);

    // catS for rows <= sl only; warp 7 loads self row + precomputes inv-norm
    if (tid <= sl) catS[tid] = __ldg(xb + tid * FF + 5);
    if (warp == 7) {
        const int hl = tid & 15;
        if ((tid & 31) < 16) {
            const int cs = __ldg(xb + sl * FF + 5);
            selfv[hl] = __ldg(reinterpret_cast<const float4*>(E + (size_t)cs * DD) + hl);
        }
        __syncwarp();
        const float4 s = selfv[hl];                       // lanes 16-31 mirror 0-15
        float q = s.x * s.x + s.y * s.y + s.z * s.z + s.w * s.w;
        q += __shfl_xor_sync(0xffffffffu, q, 8);
        q += __shfl_xor_sync(0xffffffffu, q, 4);
        q += __shfl_xor_sync(0xffffffffu, q, 2);
        q += __shfl_xor_sync(0xffffffffu, q, 1);
        if (tid == 224) invns = rsqrtf(q + 1e-8f);
    }
    __syncthreads();

    // ---- Phase A: fused gather + partials (packed f32x2 math), rows l <= sl ----
    {
        const int rg = tid >> 3;          // row within 32-row tile
        const int j8 = tid & 7;           // owns float4 slices j8 and j8+8
        F4U2 sa, sb;
        sa.f4 = selfv[j8];
        sb.f4 = selfv[j8 + 8];
        const u64 sa0 = sa.u2[0], sa1 = sa.u2[1];
        const u64 sb0 = sb.u2[0], sb1 = sb.u2[1];
        #pragma unroll
        for (int it = 0; it < 7; ++it) {
            const int l = it * 32 + rg;
            if (l <= sl) {                // warp-uniform except one boundary warp
                const int c = catS[l];
                const float4* rp = reinterpret_cast<const float4*>(E + (size_t)c * DD);
                F4U2 va, vb;
                va.f4 = __ldg(rp + j8);
                vb.f4 = __ldg(rp + j8 + 8);
                u64 d2, q2;
                MUL2(d2, va.u2[0], sa0);
                FMA2(d2, va.u2[1], sa1, d2);
                FMA2(d2, vb.u2[0], sb0, d2);
                FMA2(d2, vb.u2[1], sb1, d2);
                MUL2(q2, va.u2[0], va.u2[0]);
                FMA2(q2, va.u2[1], va.u2[1], q2);
                FMA2(q2, vb.u2[0], vb.u2[0], q2);
                FMA2(q2, vb.u2[1], vb.u2[1], q2);
                const float2 dd = unpack2(d2);
                const float2 qq = unpack2(q2);
                // rotation swizzle: partial j8 of row l -> 16B chunk ((j8>>1)+(l>>1))&3
                const int byteoff = l * 64 + ((((j8 >> 1) + (l >> 1)) & 3) << 4)
                                  + ((j8 & 1) << 3);
                *reinterpret_cast<float2*>(reinterpret_cast<char*>(partials) + byteoff)
                    = make_float2(dd.x + dd.y, qq.x + qq.y);
            }
        }
    }
    __syncthreads();

    // ---- Phase B: thread-per-row reduction, only rows <= sl ----
    float dot = 0.f, ssq = 0.f;
    if (tid <= sl) {
        const char* base = reinterpret_cast<const char*>(partials) + tid * 64;
        const int rot = (tid >> 1) & 3;
        #pragma unroll
        for (int k = 0; k < 4; ++k) {     // logical chunk order fixed (bit-exact dups)
            const float4 c = *reinterpret_cast<const float4*>(base + (((k + rot) & 3) << 4));
            dot += c.x + c.z;
            ssq += c.y + c.w;
        }
    }
    const float sim = (tid < sl) ? dot * rsqrtf(ssq + 1e-8f) * invns : -2.0f;
    const unsigned long long myKey =
        ((unsigned long long)__float_as_uint(sim) << 32) | (unsigned)(LL - 1 - tid);
    if (tid < 224) simF[tid] = sim;       // 200..223 pad = -2.0f, inert
    __syncthreads();

    // ---- rank-select among the first sl keys only (float fast path) ----
    int rank = LL;
    if (tid < sl) {
        int r = 0;
        const float4* p = reinterpret_cast<const float4*>(simF);
        const int nj = (sl + 3) >> 2;
        for (int j = 0; j < nj; ++j) {            // broadcast LDS.128
            const float4 k = p[j];
            r += (k.x > sim);
            r += (k.y > sim);
            r += (k.z > sim);
            r += (k.w > sim);
        }
        rank = r;
        if (r < KK) selKey[r] = myKey;
    }
    __syncthreads();                               // publish selKey

    // tie inside top-K -> two threads shared a slot -> loser detects; rare
    const int pred = (rank < KK) && (selKey[rank] != myKey);
    if (__syncthreads_or(pred)) {
        // exact tie-aware recount: key_j > myKey <=> fj > f || (fj == f && j < tid)
        if (tid < sl) {
            int r2 = 0;
            for (int j = 0; j < sl; ++j) {
                const float fj = simF[j];
                r2 += (fj > sim) || (fj == sim && j < tid);
            }
            if (r2 < KK) selKey[r2] = myKey;
        }
        __syncthreads();
    }

    // ---- warp 0 only: sort 15 by ascending index, emit sim_topk + x_out ----
    if (warp == 0) {
        if (tid < KK) {
            const unsigned long long mk = selKey[tid];
            const unsigned myLow = (unsigned)mk;    // 199 - l (larger = smaller l)
            int pos = 0;
            #pragma unroll
            for (int j = 0; j < KK; ++j) pos += ((unsigned)selKey[j] > myLow);
            sortedL[pos] = LL - 1 - (int)myLow;
            out[(size_t)BB * ((KK + 1) * FF) + (size_t)b * KK + pos]
                = __uint_as_float((unsigned)(mk >> 32));
        }
        if (tid == KK) sortedL[KK] = sl;
        __syncwarp();
        // x_out: 16 rows x 8 feats as float, 2 lanes per row (int4 -> float4)
        const int r    = tid >> 1;
        const int half = tid & 1;
        const int l = sortedL[r];
        const int4 v = __ldg(reinterpret_cast<const int4*>(xb + l * FF) + half);
        const float4 f = make_float4((float)v.x, (float)v.y, (float)v.z, (float)v.w);
        reinterpret_cast<float4*>(out + (size_t)b * ((KK + 1) * FF))[tid] = f;
    }
}

extern "C" void kernel_launch(void* const* d_in, const int* in_sizes, int n_in,
                              void* d_out, int out_size) {
    const int*   x  = (const int*)d_in[0];   // x: [4096, 200, 8] int32
    const int*   sl = (const int*)d_in[1];   // self_loc: [4096] int32
    const float* E  = (const float*)d_in[2]; // E: [100001, 64] float32
    float* out = (float*)d_out;

    search_predict_kernel<<<BB, 256, SMEM_BYTES>>>(x, sl, E, out);
}